// round 13
// baseline (speedup 1.0000x reference)
#include <cuda_runtime.h>
#include <cuda_bf16.h>
#include <cstdint>

// Problem constants (B=256, N=128, D=512)
#define BN    32768
#define DIM   512

// ---------------- device scratch (no allocations allowed) ----------------
__device__ unsigned char g_x8T[DIM * (size_t)BN]; // x^T in e4m3, [d][k] (16.7MB, L2-resident)
__device__ float  g_E4[4][DIM * DIM];             // 4 e-split partials of E = 0.5*diag(r) - V V^T
__device__ float  g_diag[DIM];                    // exact Sum_k x_kd^2 (fp32). Zero at launch start.
__device__ double g_S;                            // off-diagonal interaction accumulator
__device__ unsigned g_cnt;                        // k_gram completion counter

__device__ const int c_mt[10] = {0,0,0,0,1,1,1,2,2,3};
__device__ const int c_nt[10] = {0,1,2,3,1,2,3,2,3,3};

// ---------------- helpers ----------------
__device__ __forceinline__ unsigned smem_u32(const void* p) {
    return (unsigned)__cvta_generic_to_shared(p);
}
__device__ __forceinline__ void ldsm4(unsigned* r, unsigned addr) {
    asm volatile("ldmatrix.sync.aligned.m8n8.x4.shared.b16 {%0,%1,%2,%3}, [%4];"
                 : "=r"(r[0]), "=r"(r[1]), "=r"(r[2]), "=r"(r[3])
                 : "r"(addr));
}
__device__ __forceinline__ void mma_fp8(float* c, const unsigned* a, unsigned b0, unsigned b1) {
    asm volatile(
        "mma.sync.aligned.m16n8k32.row.col.f32.e4m3.e4m3.f32 "
        "{%0,%1,%2,%3}, {%4,%5,%6,%7}, {%8,%9}, {%0,%1,%2,%3};"
        : "+f"(c[0]), "+f"(c[1]), "+f"(c[2]), "+f"(c[3])
        : "r"(a[0]), "r"(a[1]), "r"(a[2]), "r"(a[3]), "r"(b0), "r"(b1));
}
__device__ __forceinline__ unsigned short f2_e4m3x2(float hi, float lo) {
    unsigned short v;
    asm("{\n\t.reg .b16 t;\n\tcvt.rn.satfinite.e4m3x2.f32 t, %1, %2;\n\tmov.b16 %0, t;\n\t}"
        : "=h"(v) : "f"(hi), "f"(lo));
    return v;   // low byte = lo, high byte = hi
}
__device__ __forceinline__ void cpasync16(unsigned saddr, const void* g) {
    asm volatile("cp.async.cg.shared.global [%0], [%1], 16;" :: "r"(saddr), "l"(g));
}
__device__ __forceinline__ void cp_commit() {
    asm volatile("cp.async.commit_group;");
}
template <int N>
__device__ __forceinline__ void cp_wait() {
    asm volatile("cp.async.wait_group %0;" :: "n"(N));
}

// ---------------- K1: merged prep ---------------------------------------
// blocks [0,256):   E partials (64 tiles x 4 e-splits) -> plain stores to g_E4[es]
// blocks [256,2304): linear part + exact column sums-of-squares + fp8 transpose
__global__ __launch_bounds__(256) void k_prep(const float* __restrict__ x,
                                              const float* __restrict__ W,
                                              const float* __restrict__ bias,
                                              const float* __restrict__ V,
                                              float* __restrict__ out) {
    __shared__ float sVa[32 * 68];
    __shared__ float sVb[32 * 68];
    __shared__ unsigned short s16[DIM * 9];   // transpose cells, pitch 9 u16 (18B)
    __shared__ float sdiag[DIM];
    const int tid = threadIdx.x;
    const int blk = blockIdx.x;

    if (blk < 256) {
        if (blk == 0 && tid == 0) { g_S = 0.0; g_cnt = 0u; }
        const int tile = blk >> 2, es = blk & 3;
        const int di = (tile >> 3) * 64, dj = (tile & 7) * 64;
        const int e0 = es * 128;
        const int tr = tid >> 4, tc = tid & 15;

        float acc[4][4];
#pragma unroll
        for (int i = 0; i < 4; i++)
#pragma unroll
            for (int j = 0; j < 4; j++) acc[i][j] = 0.f;

        for (int ch = 0; ch < 4; ch++) {
            __syncthreads();
#pragma unroll
            for (int i = 0; i < 8; i++) {
                int idx = tid + i * 256;
                int rr = idx >> 5, cc = idx & 31;
                sVa[cc * 68 + rr] = V[(size_t)(di + rr) * DIM + e0 + ch * 32 + cc];
                sVb[cc * 68 + rr] = V[(size_t)(dj + rr) * DIM + e0 + ch * 32 + cc];
            }
            __syncthreads();
#pragma unroll 4
            for (int ec = 0; ec < 32; ec++) {
                float4 av = reinterpret_cast<const float4*>(sVa)[ec * 17 + tr];
                float4 bv = reinterpret_cast<const float4*>(sVb)[ec * 17 + tc];
                float a4[4] = {av.x, av.y, av.z, av.w};
                float b4[4] = {bv.x, bv.y, bv.z, bv.w};
#pragma unroll
                for (int i = 0; i < 4; i++)
#pragma unroll
                    for (int j = 0; j < 4; j++) acc[i][j] += a4[i] * b4[j];
            }
        }
        float* Edst = g_E4[es];
#pragma unroll
        for (int i = 0; i < 4; i++) {
            int row = di + tr * 4 + i;
            float ev[4];
#pragma unroll
            for (int j = 0; j < 4; j++) {
                int col = dj + tc * 4 + j;
                float c = acc[i][j];
                ev[j] = (row == col) ? (-0.5f * c) : (-c);
            }
            float4 e = {ev[0], ev[1], ev[2], ev[3]};
            *reinterpret_cast<float4*>(&Edst[(size_t)row * DIM + dj + tc * 4]) = e;
        }
    } else {
        // ---------- linear + fp8 transpose + diag sums : 16 k-rows per CTA ----------
        float* sW = sVa;
        for (int i = tid; i < DIM; i += 256) sW[i] = W[i];
        sdiag[tid] = 0.f;
        sdiag[tid + 256] = 0.f;
        __syncthreads();

        const int warp = tid >> 5, lane = tid & 31;
        const int kbase = (blk - 256) * 16;
        const int rbase = kbase + warp * 2;
        const float4* wr = reinterpret_cast<const float4*>(sW);
        const float4 w0 = wr[2 * lane],      w1 = wr[2 * lane + 1];
        const float4 w2 = wr[64 + 2 * lane], w3 = wr[64 + 2 * lane + 1];

        const float4* xr0 = reinterpret_cast<const float4*>(x + (size_t)rbase * DIM);
        const float4* xr1 = reinterpret_cast<const float4*>(x + (size_t)(rbase + 1) * DIM);
        float4 a0[4], a1[4];
        a0[0] = xr0[2 * lane];      a0[1] = xr0[2 * lane + 1];
        a0[2] = xr0[64 + 2 * lane]; a0[3] = xr0[64 + 2 * lane + 1];
        a1[0] = xr1[2 * lane];      a1[1] = xr1[2 * lane + 1];
        a1[2] = xr1[64 + 2 * lane]; a1[3] = xr1[64 + 2 * lane + 1];

        float A0[16], A1[16];
#pragma unroll
        for (int q = 0; q < 4; q++) {
            *reinterpret_cast<float4*>(&A0[4 * q]) = a0[q];
            *reinterpret_cast<float4*>(&A1[4 * q]) = a1[q];
        }

        // fp8 pack + smem transpose + diag partials
#pragma unroll
        for (int j = 0; j < 16; j++) {
            int d = (j < 8) ? (8 * lane + j) : (256 + 8 * lane + (j - 8));
            float v0 = A0[j], v1 = A1[j];
            s16[d * 9 + warp] = f2_e4m3x2(v1, v0);   // low byte = even k row
            atomicAdd(&sdiag[d], v0 * v0 + v1 * v1);
        }

        // linear dots
        float s0 = a0[0].x * w0.x + a0[0].y * w0.y + a0[0].z * w0.z + a0[0].w * w0.w
                 + a0[1].x * w1.x + a0[1].y * w1.y + a0[1].z * w1.z + a0[1].w * w1.w
                 + a0[2].x * w2.x + a0[2].y * w2.y + a0[2].z * w2.z + a0[2].w * w2.w
                 + a0[3].x * w3.x + a0[3].y * w3.y + a0[3].z * w3.z + a0[3].w * w3.w;
        float s1 = a1[0].x * w0.x + a1[0].y * w0.y + a1[0].z * w0.z + a1[0].w * w0.w
                 + a1[1].x * w1.x + a1[1].y * w1.y + a1[1].z * w1.z + a1[1].w * w1.w
                 + a1[2].x * w2.x + a1[2].y * w2.y + a1[2].z * w2.z + a1[2].w * w2.w
                 + a1[3].x * w3.x + a1[3].y * w3.y + a1[3].z * w3.z + a1[3].w * w3.w;
#pragma unroll
        for (int off = 16; off; off >>= 1) {
            s0 += __shfl_xor_sync(0xffffffffu, s0, off);
            s1 += __shfl_xor_sync(0xffffffffu, s1, off);
        }
        if (lane == 0) {
            out[rbase]     = s0 + bias[0];
            out[rbase + 1] = s1 + bias[0];
        }
        __syncthreads();

        // transpose readout: thread t -> d rows 2t, 2t+1 (16 bytes each)
#pragma unroll
        for (int q = 0; q < 2; q++) {
            int d = 2 * tid + q;
            const unsigned short* row = &s16[d * 9];
            uint4 p;
            p.x = (unsigned)row[0] | ((unsigned)row[1] << 16);
            p.y = (unsigned)row[2] | ((unsigned)row[3] << 16);
            p.z = (unsigned)row[4] | ((unsigned)row[5] << 16);
            p.w = (unsigned)row[6] | ((unsigned)row[7] << 16);
            *reinterpret_cast<uint4*>(&g_x8T[(size_t)d * BN + kbase]) = p;
        }
        // diag partials -> global (512 atomics per CTA)
        atomicAdd(&g_diag[tid],       sdiag[tid]);
        atomicAdd(&g_diag[tid + 256], sdiag[tid + 256]);
    }
}

// ---------------- K2: Gram via e4m3 mma.sync (2x FLOP/instr) -------------
// 10 upper-triangular 128x128 tiles x 28 k-splits = 280 CTAs, 256 threads.
// Warp tile 64x32 (2x4 grid). smem tiles [d][k] pitch 80B, non-trans ldmatrix.
#define KC 64                        // k-bytes per stage
#define PITCH 80                     // 64 data + 16 pad
#define TILEB (128 * PITCH)          // 10240 B
#define STAGEB (2 * TILEB)
#define NSTG 4
#define NSPLIT 28
#define NBLK  (10 * NSPLIT)
#define NCHV  (BN / KC)              // 512

__global__ __launch_bounds__(256, 2) void k_gram(float* __restrict__ out) {
    extern __shared__ __align__(16) unsigned char dsm[];
    __shared__ float red[256];
    __shared__ double dred[256];
    __shared__ int slast;
    __shared__ double sS;

    const int tid  = threadIdx.x;
    const int bid  = blockIdx.x;
    const int tile = bid % 10;
    const int ks   = bid / 10;
    const int mt = c_mt[tile], nt = c_nt[tile];
    const bool diag = (mt == nt);
    const int m0 = mt * 128, n0 = nt * 128;
    const int ch0 = (ks * NCHV) / NSPLIT;
    const int ch1 = ((ks + 1) * NCHV) / NSPLIT;
    const int nst = ch1 - ch0;               // 18 or 19 stages
    const size_t k0 = (size_t)ch0 * KC;

    const int lane = tid & 31, warp = tid >> 5;
    const int wm0 = (warp >> 2) * 64;
    const int wn0 = (warp & 3) * 32;
    const int r8 = lane & 7, sel = lane >> 3;

    // ldmatrix (non-trans) address offsets within a stage tile
    unsigned aoff[4], boff[2];
#pragma unroll
    for (int mi = 0; mi < 4; mi++)
        aoff[mi] = (unsigned)((wm0 + mi * 16 + r8 + 8 * (sel & 1)) * PITCH + 16 * (sel >> 1));
#pragma unroll
    for (int p = 0; p < 2; p++)
        boff[p] = (unsigned)((wn0 + 16 * p + r8 + 8 * (sel >> 1)) * PITCH + 16 * (sel & 1));

    // loader: 512 16B chunks per matrix; thread covers d0 and d0+64
    const int d0 = tid >> 2, kb = (tid & 3) * 16;
    const unsigned char* gA0 = g_x8T + (size_t)(m0 + d0) * BN + k0 + kb;
    const unsigned char* gA1 = gA0 + (size_t)64 * BN;
    const unsigned char* gB0 = g_x8T + (size_t)(n0 + d0) * BN + k0 + kb;
    const unsigned char* gB1 = gB0 + (size_t)64 * BN;
    const unsigned sbase = smem_u32(dsm);
    const unsigned soA0 = (unsigned)(d0 * PITCH + kb);
    const unsigned soA1 = (unsigned)((d0 + 64) * PITCH + kb);

    auto issue = [&](int s) {
        const unsigned sb = sbase + (unsigned)(s & 3) * STAGEB;
        const size_t go = (size_t)s * KC;
        cpasync16(sb + soA0, gA0 + go);
        cpasync16(sb + soA1, gA1 + go);
        if (!diag) {
            cpasync16(sb + TILEB + soA0, gB0 + go);
            cpasync16(sb + TILEB + soA1, gB1 + go);
        }
        cp_commit();
    };

    float acc[4][4][4];
#pragma unroll
    for (int i = 0; i < 4; i++)
#pragma unroll
        for (int j = 0; j < 4; j++)
#pragma unroll
            for (int q = 0; q < 4; q++) acc[i][j][q] = 0.f;

    issue(0); issue(1); issue(2);

    for (int s = 0; s < nst; s++) {
        if (s + 2 < nst)      cp_wait<2>();
        else if (s + 1 < nst) cp_wait<1>();
        else                  cp_wait<0>();
        __syncthreads();

        const unsigned tb = sbase + (unsigned)(s & 3) * STAGEB;
        const unsigned bb = diag ? tb : (tb + TILEB);
#pragma unroll
        for (int kc = 0; kc < 2; kc++) {
            const unsigned ka = kc * 32;
            unsigned afr[4][4];
#pragma unroll
            for (int mi = 0; mi < 4; mi++)
                ldsm4(afr[mi], tb + aoff[mi] + ka);
            unsigned bq[2][4];
#pragma unroll
            for (int p = 0; p < 2; p++)
                ldsm4(bq[p], bb + boff[p] + ka);
#pragma unroll
            for (int mi = 0; mi < 4; mi++) {
                mma_fp8(acc[mi][0], afr[mi], bq[0][0], bq[0][1]);
                mma_fp8(acc[mi][1], afr[mi], bq[0][2], bq[0][3]);
                mma_fp8(acc[mi][2], afr[mi], bq[1][0], bq[1][1]);
                mma_fp8(acc[mi][3], afr[mi], bq[1][2], bq[1][3]);
            }
        }
        if (s + 3 < nst) issue(s + 3);
    }

    // ---- fused trace epilogue (diagonal elements excluded on diag tiles) ----
    const int g = lane >> 2, t4 = lane & 3;
    float fsum = 0.f;
#pragma unroll
    for (int mi = 0; mi < 4; mi++) {
#pragma unroll
        for (int ni = 0; ni < 4; ni++) {
            int row0 = m0 + wm0 + mi * 16 + g;
            int col0 = n0 + wn0 + ni * 8 + 2 * t4;
            size_t i0 = (size_t)row0 * DIM + col0;
            size_t i1 = (size_t)(row0 + 8) * DIM + col0;
            float ex = 0.f, ey = 0.f, fx = 0.f, fy = 0.f;
#pragma unroll
            for (int es = 0; es < 4; es++) {
                float2 e0 = *reinterpret_cast<const float2*>(&g_E4[es][i0]);
                float2 e1 = *reinterpret_cast<const float2*>(&g_E4[es][i1]);
                ex += e0.x; ey += e0.y;
                fx += e1.x; fy += e1.y;
            }
            if (diag) {   // exact-diagonal handled separately in fp32
                if (row0 == col0)          ex = 0.f;
                else if (row0 == col0 + 1) ey = 0.f;
                if (row0 + 8 == col0)          fx = 0.f;
                else if (row0 + 8 == col0 + 1) fy = 0.f;
            }
            fsum += acc[mi][ni][0] * ex + acc[mi][ni][1] * ey
                  + acc[mi][ni][2] * fx + acc[mi][ni][3] * fy;
        }
    }
    red[tid] = fsum;
    __syncthreads();
    for (int o = 128; o; o >>= 1) {
        if (tid < o) red[tid] += red[tid + o];
        __syncthreads();
    }
    if (tid == 0) {
        double w = diag ? 1.0 : 2.0;
        atomicAdd(&g_S, w * (double)red[0]);
        __threadfence();
        unsigned old = atomicAdd(&g_cnt, 1u);
        slast = (old == NBLK - 1) ? 1 : 0;
        if (slast) sS = atomicAdd(&g_S, 0.0);   // all contributions visible
    }
    __syncthreads();

    // ---- last CTA: exact diagonal term + broadcast ----
    if (slast) {
        double part = 0.0;
#pragma unroll
        for (int q = 0; q < 2; q++) {
            int d = tid + q * 256;
            float edd = 0.f;
#pragma unroll
            for (int es = 0; es < 4; es++) edd += g_E4[es][(size_t)d * (DIM + 1)];
            part += (double)g_diag[d] * (double)edd;
            g_diag[d] = 0.f;                    // re-zero for next launch
        }
        dred[tid] = part;
        __syncthreads();
        for (int o = 128; o; o >>= 1) {
            if (tid < o) dred[tid] += dred[tid + o];
            __syncthreads();
        }
        const float I = (float)(sS + dred[0]);
        float4* o4 = reinterpret_cast<float4*>(out);
#pragma unroll 4
        for (int i = tid; i < BN / 4; i += 256) {
            float4 v = o4[i];
            v.x += I; v.y += I; v.z += I; v.w += I;
            o4[i] = v;
        }
    }
}

// ---------------- launch ----------------
extern "C" void kernel_launch(void* const* d_in, const int* in_sizes, int n_in,
                              void* d_out, int out_size) {
    const float* x = (const float*)d_in[0];   // [256,128,512]
    const float* W = (const float*)d_in[1];   // [1,512]
    const float* b = (const float*)d_in[2];   // [1]
    const float* V = (const float*)d_in[3];   // [512,512]
    float* out = (float*)d_out;               // [32768,1]

    cudaFuncSetAttribute(k_gram, cudaFuncAttributeMaxDynamicSharedMemorySize, NSTG * STAGEB);
    k_prep <<<256 + BN / 16, 256>>>(x, W, b, V, out);
    k_gram <<<NBLK, 256, NSTG * STAGEB>>>(out);
}